// round 2
// baseline (speedup 1.0000x reference)
#include <cuda_runtime.h>
#include <stdint.h>

// KANLayer: BATCH=512, NUM_IN=NUM_OUT=128, SIZE=16384, K=3, G=5 (8 coefs)
// Outputs (tuple order): y[512,128], pre.T[512,16384], psp.T[512,16384], pac.T[512,16384]
// pre.T[b,s] = x[b, s%128] -> Cox-de-Boor basis hoisted out of the o-loop.

#define NUM_IN   128
#define SIZE_T   16384
#define BATCH    512
#define SCHUNK   1024                 // s per block (8 o-rows x 128 i)
#define OCHUNK   (SCHUNK / NUM_IN)    // 8
#define BTILE    4                    // batches per block
#define BQ       2                    // batches per thread
#define THREADS  256
#define NCHUNK   (SIZE_T / SCHUNK)    // 16
#define NBGRP    (BATCH / BTILE)      // 128

// Degree-3 Cox-de-Boor on a uniform grid (knots are a tiled linspace ->
// all denominators are p*h -> division-free recursion).
__device__ __forceinline__ void basis8(float xv, const float* __restrict__ g,
                                       float* __restrict__ Bv)
{
    float e[12];
    const float h = (g[5] - g[0]) * 0.2f;
    e[3] = g[0]; e[4] = g[1]; e[5] = g[2]; e[6] = g[3]; e[7] = g[4]; e[8] = g[5];
    e[2] = g[0] - h;  e[1] = g[0] - 2.0f * h;  e[0] = g[0] - 3.0f * h;
    e[9] = g[5] + h;  e[10] = g[5] + 2.0f * h; e[11] = g[5] + 3.0f * h;
    const float rh = __frcp_rn(h);

    float B[11];
#pragma unroll
    for (int j = 0; j < 11; j++)
        B[j] = (xv >= e[j] && xv < e[j + 1]) ? 1.0f : 0.0f;

#pragma unroll
    for (int p = 1; p <= 3; p++) {
        const float rhp = rh * (p == 1 ? 1.0f : (p == 2 ? 0.5f : (1.0f / 3.0f)));
#pragma unroll
        for (int j = 0; j + p < 11; j++) {
            B[j] = (xv - e[j]) * rhp * B[j] + (e[j + p + 1] - xv) * rhp * B[j + 1];
        }
    }
#pragma unroll
    for (int j = 0; j < 8; j++) Bv[j] = B[j];
}

extern "C" __global__ void __launch_bounds__(THREADS, 4)
kan_main(const float* __restrict__ x,
         const float* __restrict__ scale_b,
         const float* __restrict__ scale_sp,
         const float* __restrict__ coef,
         const float* __restrict__ mask,
         const float* __restrict__ knots,
         float* __restrict__ y,
         float* __restrict__ pre,
         float* __restrict__ psp,
         float* __restrict__ pac)
{
    __shared__ float4 s_coef[SCHUNK * 2];   // 32 KB: coef * mask
    __shared__ float  s_sb[SCHUNK];         //  4 KB
    __shared__ float  s_ss[SCHUNK];         //  4 KB

    const int bg    = blockIdx.x >> 4;      // 128 batch groups
    const int chunk = blockIdx.x & 15;      // 16 s-chunks
    const int sbase = chunk * SCHUNK;
    const int bbase = bg * BTILE;

    const int tid  = threadIdx.x;
    const int i    = tid & (NUM_IN - 1);    // s % 128 owned by this thread
    const int slot = tid >> 7;              // 0 / 1
    const int b0   = bbase + slot * BQ;

    // ---- per-(b,i) inputs first (overlap LDG latency with staging) ----
    float gl[6];
    {
        const float* g = knots + (size_t)i * 6;
#pragma unroll
        for (int m = 0; m < 6; m++) gl[m] = __ldg(g + m);
    }
    float xv[BQ];
#pragma unroll
    for (int q = 0; q < BQ; q++)
        xv[q] = __ldg(x + (size_t)(b0 + q) * NUM_IN + i);

    // ---- stage s-chunk tables into SMEM (mask folded into coef) ----
    const float4* cg = (const float4*)coef;
    for (int idx = tid; idx < SCHUNK * 2; idx += THREADS) {
        const int row = idx >> 1;
        const float m = __ldg(mask + sbase + row);
        float4 c = __ldg(cg + (size_t)sbase * 2 + idx);
        c.x *= m; c.y *= m; c.z *= m; c.w *= m;
        s_coef[idx] = c;
    }
    for (int idx = tid; idx < SCHUNK; idx += THREADS) {
        s_sb[idx] = __ldg(scale_b  + sbase + idx);
        s_ss[idx] = __ldg(scale_sp + sbase + idx);
    }

    // ---- basis + silu, computed ONCE per (b,i), reused over all o ----
    float Bv[BQ][8], sl[BQ], acc[BQ];
#pragma unroll
    for (int q = 0; q < BQ; q++) {
        sl[q]  = xv[q] / (1.0f + __expf(-xv[q]));   // silu
        acc[q] = 0.0f;
        basis8(xv[q], gl, Bv[q]);
    }
    __syncthreads();

    // per-thread output base pointers (incremented by 128 each o-row)
    const size_t base0 = (size_t)b0 * SIZE_T + (size_t)sbase + i;
    float* p0 = pre + base0;
    float* p1 = psp + base0;
    float* p2 = pac + base0;

    // ---- main loop: 8 o-rows x 2 batches per thread ----
#pragma unroll 4
    for (int o = 0; o < OCHUNK; o++) {
        const int    rl  = o * NUM_IN + i;
        const float4 cA  = s_coef[rl * 2];
        const float4 cB  = s_coef[rl * 2 + 1];
        const float  sbv = s_sb[rl];
        const float  ssv = s_ss[rl];
        const int    off = o * NUM_IN;
#pragma unroll
        for (int q = 0; q < BQ; q++) {
            const float sp = cA.x * Bv[q][0] + cA.y * Bv[q][1]
                           + cA.z * Bv[q][2] + cA.w * Bv[q][3]
                           + cB.x * Bv[q][4] + cB.y * Bv[q][5]
                           + cB.z * Bv[q][6] + cB.w * Bv[q][7];
            const float pa = sbv * sl[q] + ssv * sp;
            const size_t idx = (size_t)q * SIZE_T + off;
            p0[idx] = xv[q];
            p1[idx] = sp;
            p2[idx] = pa;
            acc[q] += pa;
        }
    }

    // ---- y[b,i] partial reduction (one RED per (b,i) per block) ----
#pragma unroll
    for (int q = 0; q < BQ; q++)
        atomicAdd(y + (size_t)(b0 + q) * NUM_IN + i, acc[q]);
}

extern "C" void kernel_launch(void* const* d_in, const int* in_sizes, int n_in,
                              void* d_out, int out_size)
{
    const float* x    = (const float*)d_in[0];
    const float* sb   = (const float*)d_in[1];
    const float* ss   = (const float*)d_in[2];
    const float* coef = (const float*)d_in[3];
    const float* mask = (const float*)d_in[4];
    const float* kn   = (const float*)d_in[5];

    float* y   = (float*)d_out;
    float* pre = y   + (size_t)BATCH * NUM_IN;
    float* psp = pre + (size_t)BATCH * SIZE_T;
    float* pac = psp + (size_t)BATCH * SIZE_T;

    cudaMemsetAsync(y, 0, (size_t)BATCH * NUM_IN * sizeof(float), 0);
    kan_main<<<NBGRP * NCHUNK, THREADS>>>(x, sb, ss, coef, mask, kn,
                                          y, pre, psp, pac);
}

// round 3
// speedup vs baseline: 1.0760x; 1.0760x over previous
#include <cuda_runtime.h>
#include <stdint.h>

// KANLayer: BATCH=512, NUM_IN=NUM_OUT=128, SIZE=16384, K=3, G=5 (8 coefs)
// Outputs (tuple order): y[512,128], pre.T[512,16384], psp.T[512,16384], pac.T[512,16384]
// pre.T[b,s] = x[b, s%128] -> Cox-de-Boor basis hoisted out of the o-loop.
// Tables (coef/mask/scales, 640 KB) are L2/L1-resident: read them directly
// with __ldg instead of staging through SMEM (no STS, no sync, no smem cap).

#define NUM_IN   128
#define SIZE_T   16384
#define BATCH    512
#define SCHUNK   1024                 // s per block (8 o-rows x 128 i)
#define OCHUNK   (SCHUNK / NUM_IN)    // 8
#define BTILE    8                    // batches per block
#define BQ       4                    // batches per thread
#define THREADS  256
#define NCHUNK   (SIZE_T / SCHUNK)    // 16
#define NBGRP    (BATCH / BTILE)      // 64

// Degree-3 Cox-de-Boor on a uniform grid (knots are a tiled linspace ->
// all denominators are p*h -> division-free recursion).
__device__ __forceinline__ void basis8(float xv, const float* __restrict__ g,
                                       float* __restrict__ Bv)
{
    float e[12];
    const float h = (g[5] - g[0]) * 0.2f;
    e[3] = g[0]; e[4] = g[1]; e[5] = g[2]; e[6] = g[3]; e[7] = g[4]; e[8] = g[5];
    e[2] = g[0] - h;  e[1] = g[0] - 2.0f * h;  e[0] = g[0] - 3.0f * h;
    e[9] = g[5] + h;  e[10] = g[5] + 2.0f * h; e[11] = g[5] + 3.0f * h;
    const float rh = __frcp_rn(h);

    float B[11];
#pragma unroll
    for (int j = 0; j < 11; j++)
        B[j] = (xv >= e[j] && xv < e[j + 1]) ? 1.0f : 0.0f;

#pragma unroll
    for (int p = 1; p <= 3; p++) {
        const float rhp = rh * (p == 1 ? 1.0f : (p == 2 ? 0.5f : (1.0f / 3.0f)));
#pragma unroll
        for (int j = 0; j + p < 11; j++) {
            B[j] = (xv - e[j]) * rhp * B[j] + (e[j + p + 1] - xv) * rhp * B[j + 1];
        }
    }
#pragma unroll
    for (int j = 0; j < 8; j++) Bv[j] = B[j];
}

extern "C" __global__ void __launch_bounds__(THREADS, 4)
kan_main(const float* __restrict__ x,
         const float* __restrict__ scale_b,
         const float* __restrict__ scale_sp,
         const float* __restrict__ coef,
         const float* __restrict__ mask,
         const float* __restrict__ knots,
         float* __restrict__ y,
         float* __restrict__ pre,
         float* __restrict__ psp,
         float* __restrict__ pac)
{
    const int bg    = blockIdx.x >> 4;      // 64 batch groups
    const int chunk = blockIdx.x & 15;      // 16 s-chunks
    const int sbase = chunk * SCHUNK;
    const int bbase = bg * BTILE;

    const int tid  = threadIdx.x;
    const int i    = tid & (NUM_IN - 1);    // s % 128 owned by this thread
    const int slot = tid >> 7;              // 0 / 1
    const int b0   = bbase + slot * BQ;

    // ---- per-(b,i) basis + silu, computed ONCE, reused over all o ----
    float gl[6];
    {
        const float* g = knots + (size_t)i * 6;
#pragma unroll
        for (int m = 0; m < 6; m++) gl[m] = __ldg(g + m);
    }
    float Bv[BQ][8], xv[BQ], sl[BQ], acc[BQ];
#pragma unroll
    for (int q = 0; q < BQ; q++) {
        xv[q]  = __ldg(x + (size_t)(b0 + q) * NUM_IN + i);
        sl[q]  = xv[q] / (1.0f + __expf(-xv[q]));   // silu
        acc[q] = 0.0f;
        basis8(xv[q], gl, Bv[q]);
    }

    // per-thread output base pointers (advance 128 per o-row)
    const size_t base0 = (size_t)b0 * SIZE_T + (size_t)sbase + i;
    float* p0 = pre + base0;
    float* p1 = psp + base0;
    float* p2 = pac + base0;

    const float4* cg = (const float4*)coef;   // 2 float4 per s-row

    // ---- main loop: 8 o-rows x 4 batches per thread ----
#pragma unroll 2
    for (int o = 0; o < OCHUNK; o++) {
        const int    s   = sbase + o * NUM_IN + i;
        const float4 cA  = __ldg(cg + (size_t)s * 2);
        const float4 cB  = __ldg(cg + (size_t)s * 2 + 1);
        const float  m   = __ldg(mask + s);
        const float  sbv = __ldg(scale_b + s);
        const float  ssv = __ldg(scale_sp + s);
        const int    off = o * NUM_IN;
#pragma unroll
        for (int q = 0; q < BQ; q++) {
            const float sp = (cA.x * Bv[q][0] + cA.y * Bv[q][1]
                            + cA.z * Bv[q][2] + cA.w * Bv[q][3]
                            + cB.x * Bv[q][4] + cB.y * Bv[q][5]
                            + cB.z * Bv[q][6] + cB.w * Bv[q][7]) * m;
            const float pa = sbv * sl[q] + ssv * sp;
            const size_t idx = (size_t)q * SIZE_T + off;
            p0[idx] = xv[q];
            p1[idx] = sp;
            p2[idx] = pa;
            acc[q] += pa;
        }
    }

    // ---- y[b,i] partial reduction (one RED per (b,i) per block) ----
#pragma unroll
    for (int q = 0; q < BQ; q++)
        atomicAdd(y + (size_t)(b0 + q) * NUM_IN + i, acc[q]);
}

extern "C" void kernel_launch(void* const* d_in, const int* in_sizes, int n_in,
                              void* d_out, int out_size)
{
    const float* x    = (const float*)d_in[0];
    const float* sb   = (const float*)d_in[1];
    const float* ss   = (const float*)d_in[2];
    const float* coef = (const float*)d_in[3];
    const float* mask = (const float*)d_in[4];
    const float* kn   = (const float*)d_in[5];

    float* y   = (float*)d_out;
    float* pre = y   + (size_t)BATCH * NUM_IN;
    float* psp = pre + (size_t)BATCH * SIZE_T;
    float* pac = psp + (size_t)BATCH * SIZE_T;

    cudaMemsetAsync(y, 0, (size_t)BATCH * NUM_IN * sizeof(float), 0);
    kan_main<<<NBGRP * NCHUNK, THREADS>>>(x, sb, ss, coef, mask, kn,
                                          y, pre, psp, pac);
}